// round 8
// baseline (speedup 1.0000x reference)
#include <cuda_runtime.h>

// BalancedLoss, fused single kernel. Per column c:
//   A_c = sum (1-t)*softplus(x),  B_c = sum t*(softplus(x)-x),  P_c = sum t
//   loss = sum_c (w0_c*A_c + w1_c*B_c) / (B*C)
// R7: 256-thread blocks, 5 CTAs/SM (40 warps/SM, regs<=51) to fix the
// latency-bound profile (nothing >65% busy at 32 warps/SM).

#define CCOLS 512
#define C4 128          // float4 groups per row
#define NBLK 740        // 5 CTAs per SM on 148 SMs
#define NTHR 256        // 2 row-lanes of 128 threads

__device__ float g_accA[CCOLS];
__device__ float g_accB[CCOLS];
__device__ float g_accP[CCOLS];
__device__ unsigned int g_done;   // zero-init; reset by last block each run

__device__ __forceinline__ float softplus_f(float x) {
    return fmaxf(x, 0.0f) + __logf(1.0f + __expf(-fabsf(x)));
}

struct Acc {
    float a0, a1, a2, a3;
    float b0, b1, b2, b3;
    float p0, p1, p2, p3;
};

__device__ __forceinline__ void bl_acc(Acc& ac, const float4& x, const float4& t) {
    float s;
    s = softplus_f(x.x); ac.a0 += s - s*t.x; ac.b0 += (s - x.x)*t.x; ac.p0 += t.x;
    s = softplus_f(x.y); ac.a1 += s - s*t.y; ac.b1 += (s - x.y)*t.y; ac.p1 += t.y;
    s = softplus_f(x.z); ac.a2 += s - s*t.z; ac.b2 += (s - x.z)*t.z; ac.p2 += t.z;
    s = softplus_f(x.w); ac.a3 += s - s*t.w; ac.b3 += (s - x.w)*t.w; ac.p3 += t.w;
}

__global__ __launch_bounds__(NTHR, 5)
void bl_fused_kernel(const float4* __restrict__ pred,
                     const float4* __restrict__ targ,
                     const float* __restrict__ pos_prop,
                     float* __restrict__ out,
                     int Bn) {
    const int tid   = threadIdx.x;
    const int cg    = tid & (C4 - 1);    // column group (cols 4cg..4cg+3)
    const int rlane = tid >> 7;          // 0..1
    const int step  = gridDim.x * 2;     // row stride (1480)

    Acc ac = {0.f,0.f,0.f,0.f, 0.f,0.f,0.f,0.f, 0.f,0.f,0.f,0.f};

    int r = blockIdx.x * 2 + rlane;

    // Main loop: 2 row-steps per trip, 4 loads front-batched (MLP_p1 = 4).
    for (; r + step < Bn; r += 2 * step) {
        const long i0 = (long)r * C4 + cg;
        const long i1 = i0 + (long)step * C4;
        const float4 x0 = __ldcs(pred + i0);
        const float4 t0 = __ldcs(targ + i0);
        const float4 x1 = __ldcs(pred + i1);
        const float4 t1 = __ldcs(targ + i1);
        bl_acc(ac, x0, t0);
        bl_acc(ac, x1, t1);
    }
    // Remainder (<= 1 row-step)
    for (; r < Bn; r += step) {
        const long i = (long)r * C4 + cg;
        const float4 x = __ldcs(pred + i);
        const float4 t = __ldcs(targ + i);
        bl_acc(ac, x, t);
    }

    // ---- intra-block reduction over the 2 row-lanes ----
    __shared__ float4 sbuf[NTHR];   // 4 KB

    sbuf[tid] = make_float4(ac.a0, ac.a1, ac.a2, ac.a3);
    __syncthreads();
    if (rlane == 0) {
        float4 u = sbuf[tid + 128];
        ac.a0 += u.x;  ac.a1 += u.y;  ac.a2 += u.z;  ac.a3 += u.w;
    }
    __syncthreads();
    sbuf[tid] = make_float4(ac.b0, ac.b1, ac.b2, ac.b3);
    __syncthreads();
    if (rlane == 0) {
        float4 u = sbuf[tid + 128];
        ac.b0 += u.x;  ac.b1 += u.y;  ac.b2 += u.z;  ac.b3 += u.w;
    }
    __syncthreads();
    sbuf[tid] = make_float4(ac.p0, ac.p1, ac.p2, ac.p3);
    __syncthreads();
    if (rlane == 0) {
        float4 u = sbuf[tid + 128];
        ac.p0 += u.x;  ac.p1 += u.y;  ac.p2 += u.z;  ac.p3 += u.w;

        const int c = cg * 4;
        atomicAdd(&g_accA[c + 0], ac.a0); atomicAdd(&g_accA[c + 1], ac.a1);
        atomicAdd(&g_accA[c + 2], ac.a2); atomicAdd(&g_accA[c + 3], ac.a3);
        atomicAdd(&g_accB[c + 0], ac.b0); atomicAdd(&g_accB[c + 1], ac.b1);
        atomicAdd(&g_accB[c + 2], ac.b2); atomicAdd(&g_accB[c + 3], ac.b3);
        atomicAdd(&g_accP[c + 0], ac.p0); atomicAdd(&g_accP[c + 1], ac.p1);
        atomicAdd(&g_accP[c + 2], ac.p2); atomicAdd(&g_accP[c + 3], ac.p3);
    }

    // ---- last-block finalize ----
    __shared__ bool s_last;
    __threadfence();
    __syncthreads();
    if (tid == 0) {
        unsigned int prev = atomicAdd(&g_done, 1u);
        s_last = (prev == gridDim.x - 1);
    }
    __syncthreads();
    if (!s_last) return;

    __threadfence();
    {
        const float Bf = (float)Bn;
        float contrib = 0.0f;

        #pragma unroll
        for (int k = 0; k < 2; k++) {
            const int c = tid + k * NTHR;       // covers 512 columns
            const float P  = g_accP[c];
            const float bn = pos_prop[c] * Bf;

            const bool  majIs1 = (P >= bn);
            const float n_maj  = majIs1 ? P : (Bf - P);
            const float n_min  = Bf - n_maj;
            const float w_maj  = bn / n_maj;
            const float w_min  = (n_min > 0.0f) ? (Bf - bn) / fmaxf(n_min, 1.0f)
                                                : 1.0f;
            const float w1 = majIs1 ? w_maj : w_min;
            const float w0 = majIs1 ? w_min : w_maj;

            contrib += w0 * g_accA[c] + w1 * g_accB[c];

            // reset state for next graph replay (deterministic)
            g_accA[c] = 0.0f;
            g_accB[c] = 0.0f;
            g_accP[c] = 0.0f;
        }
        if (tid == 0) g_done = 0u;

        __shared__ float sh[NTHR];
        sh[tid] = contrib;
        __syncthreads();
        #pragma unroll
        for (int s = NTHR / 2; s > 0; s >>= 1) {
            if (tid < s) sh[tid] += sh[tid + s];
            __syncthreads();
        }
        if (tid == 0) out[0] = sh[0] / (Bf * (float)CCOLS);
    }
}

extern "C" void kernel_launch(void* const* d_in, const int* in_sizes, int n_in,
                              void* d_out, int out_size) {
    const float* pred = (const float*)d_in[0];
    const float* targ = (const float*)d_in[1];
    const float* pp   = (const float*)d_in[2];
    const int Cc = in_sizes[2];          // 512
    const int Bn = in_sizes[0] / Cc;     // 65536

    bl_fused_kernel<<<NBLK, NTHR>>>((const float4*)pred, (const float4*)targ,
                                    pp, (float*)d_out, Bn);
}

// round 9
// speedup vs baseline: 1.3824x; 1.3824x over previous
#include <cuda_runtime.h>
#include <cstdint>

// BalancedLoss fused kernel, R9: cp.async.bulk (1D TMA) -> SMEM ring pipeline.
// Per column c: A_c = sum (1-t)*softplus(x), B_c = sum t*(softplus(x)-x),
// P_c = sum t;  loss = sum_c (w0_c*A_c + w1_c*B_c) / (B*C).
// Producer warp streams 16KB stages into a 4-stage SMEM ring; 512 consumer
// threads compute from SMEM. Removes the 64-reg cap on memory-level
// parallelism that limited the register-batched version.

#define CCOLS 512
#define C4    128            // float4 groups per row
#define NBLK  296            // 2 CTAs/SM
#define NCONS 512            // consumer threads (16 warps)
#define NTHR  544            // + 1 producer warp
#define NSTG  4              // ring stages
#define STG_F4 1024          // float4 per stage (512 pred + 512 targ)
#define CHUNK_BYTES 8192     // 512 float4 per tensor per chunk

__device__ float g_accA[CCOLS];
__device__ float g_accB[CCOLS];
__device__ float g_accP[CCOLS];
__device__ unsigned int g_done;

__device__ __forceinline__ uint32_t smem_u32(const void* p) {
    return (uint32_t)__cvta_generic_to_shared(p);
}

__device__ __forceinline__ void mbar_init(uint32_t mbar, uint32_t cnt) {
    asm volatile("mbarrier.init.shared.b64 [%0], %1;" :: "r"(mbar), "r"(cnt) : "memory");
}
__device__ __forceinline__ void mbar_expect_tx(uint32_t mbar, uint32_t bytes) {
    asm volatile("mbarrier.arrive.expect_tx.shared.b64 _, [%0], %1;"
                 :: "r"(mbar), "r"(bytes) : "memory");
}
__device__ __forceinline__ void mbar_arrive(uint32_t mbar) {
    asm volatile("mbarrier.arrive.shared.b64 _, [%0];" :: "r"(mbar) : "memory");
}
__device__ __forceinline__ void mbar_wait(uint32_t mbar, uint32_t phase) {
    asm volatile(
        "{\n\t"
        ".reg .pred P1;\n\t"
        "WAIT_LOOP_%=:\n\t"
        "mbarrier.try_wait.parity.acquire.cta.shared::cta.b64 P1, [%0], %1, 0x989680;\n\t"
        "@P1 bra.uni WAIT_DONE_%=;\n\t"
        "bra.uni WAIT_LOOP_%=;\n\t"
        "WAIT_DONE_%=:\n\t"
        "}"
        :: "r"(mbar), "r"(phase) : "memory");
}
__device__ __forceinline__ void bulk_g2s(uint32_t dst_smem, const void* src, uint32_t bytes,
                                         uint32_t mbar) {
    asm volatile(
        "cp.async.bulk.shared::cluster.global.mbarrier::complete_tx::bytes [%0], [%1], %2, [%3];"
        :: "r"(dst_smem), "l"(src), "r"(bytes), "r"(mbar) : "memory");
}

__device__ __forceinline__ float softplus_f(float x) {
    return fmaxf(x, 0.0f) + __logf(1.0f + __expf(-fabsf(x)));
}

struct Acc {
    float a0, a1, a2, a3, b0, b1, b2, b3, p0, p1, p2, p3;
};

__device__ __forceinline__ void bl_acc(Acc& ac, const float4& x, const float4& t) {
    float s;
    s = softplus_f(x.x); ac.a0 += s - s*t.x; ac.b0 += (s - x.x)*t.x; ac.p0 += t.x;
    s = softplus_f(x.y); ac.a1 += s - s*t.y; ac.b1 += (s - x.y)*t.y; ac.p1 += t.y;
    s = softplus_f(x.z); ac.a2 += s - s*t.z; ac.b2 += (s - x.z)*t.z; ac.p2 += t.z;
    s = softplus_f(x.w); ac.a3 += s - s*t.w; ac.b3 += (s - x.w)*t.w; ac.p3 += t.w;
}

__global__ __launch_bounds__(NTHR, 2)
void bl_pipe_kernel(const float4* __restrict__ pred,
                    const float4* __restrict__ targ,
                    const float* __restrict__ pos_prop,
                    float* __restrict__ out,
                    int Bn) {
    extern __shared__ float4 dsm[];            // NSTG * STG_F4 float4 = 64 KB
    __shared__ uint64_t mbar_store[2 * NSTG];  // [full0, empty0, full1, ...]
    __shared__ bool s_last;

    const int tid  = threadIdx.x;
    const int lane = tid & 31;
    const uint32_t mb0 = smem_u32(mbar_store);

    if (tid == 0) {
        #pragma unroll
        for (int s = 0; s < NSTG; s++) {
            mbar_init(mb0 + 16 * s, 1);        // full: completes via tx bytes
            mbar_init(mb0 + 16 * s + 8, 16);   // empty: one arrive per consumer warp
        }
    }
    __syncthreads();

    const int nchunk = (Bn / 4);               // 512 float4 groups per chunk = 4 rows
    const int grid = gridDim.x;

    if (tid >= NCONS) {
        // ---------------- producer warp (lane 0 of warp 16 issues) ----------
        if (lane == 0) {
            int st = 0, ph = 1;                // first empty-wait passes immediately
            for (int chunk = blockIdx.x; chunk < nchunk; chunk += grid) {
                const uint32_t full  = mb0 + 16 * st;
                const uint32_t empty = full + 8;
                mbar_wait(empty, ph);
                mbar_expect_tx(full, 2 * CHUNK_BYTES);
                const uint32_t dst = smem_u32(dsm + st * STG_F4);
                bulk_g2s(dst,               pred + (size_t)chunk * 512, CHUNK_BYTES, full);
                bulk_g2s(dst + CHUNK_BYTES, targ + (size_t)chunk * 512, CHUNK_BYTES, full);
                if (++st == NSTG) { st = 0; ph ^= 1; }
            }
        }
    } else {
        // ---------------- consumers (512 threads) ---------------------------
        Acc ac = {0.f,0.f,0.f,0.f, 0.f,0.f,0.f,0.f, 0.f,0.f,0.f,0.f};
        int st = 0, ph = 0;
        for (int chunk = blockIdx.x; chunk < nchunk; chunk += grid) {
            const uint32_t full  = mb0 + 16 * st;
            const uint32_t empty = full + 8;
            mbar_wait(full, ph);
            const float4 x = dsm[st * STG_F4 + tid];
            const float4 t = dsm[st * STG_F4 + 512 + tid];
            bl_acc(ac, x, t);
            __syncwarp();
            if (lane == 0) mbar_arrive(empty);
            if (++st == NSTG) { st = 0; ph ^= 1; }
        }
        // tail rows (Bn % 4 != 0): direct loads, block 0 only, col-preserving
        if (blockIdx.x == 0 && tid < C4) {
            for (int r = (nchunk * 4); r < Bn; r++) {
                const size_t i = (size_t)r * C4 + tid;
                const float4 x = __ldg(pred + i);
                const float4 t = __ldg(targ + i);
                bl_acc(ac, x, t);
            }
        }

        // ---- intra-block reduction over 4 row-lanes (reuse dsm after sync) --
        __syncthreads();   // NOTE: all NTHR threads participate (producer warp too)

        float4* sbuf = dsm;                    // 512 float4 scratch
        const int rlane = tid >> 7;            // 0..3

        sbuf[tid] = make_float4(ac.a0, ac.a1, ac.a2, ac.a3);
        __syncthreads();
        if (rlane == 0) {
            float4 u = sbuf[tid+128], v = sbuf[tid+256], w = sbuf[tid+384];
            ac.a0 += u.x+v.x+w.x; ac.a1 += u.y+v.y+w.y;
            ac.a2 += u.z+v.z+w.z; ac.a3 += u.w+v.w+w.w;
        }
        __syncthreads();
        sbuf[tid] = make_float4(ac.b0, ac.b1, ac.b2, ac.b3);
        __syncthreads();
        if (rlane == 0) {
            float4 u = sbuf[tid+128], v = sbuf[tid+256], w = sbuf[tid+384];
            ac.b0 += u.x+v.x+w.x; ac.b1 += u.y+v.y+w.y;
            ac.b2 += u.z+v.z+w.z; ac.b3 += u.w+v.w+w.w;
        }
        __syncthreads();
        sbuf[tid] = make_float4(ac.p0, ac.p1, ac.p2, ac.p3);
        __syncthreads();
        if (rlane == 0) {
            float4 u = sbuf[tid+128], v = sbuf[tid+256], w = sbuf[tid+384];
            ac.p0 += u.x+v.x+w.x; ac.p1 += u.y+v.y+w.y;
            ac.p2 += u.z+v.z+w.z; ac.p3 += u.w+v.w+w.w;

            const int c = (tid & (C4 - 1)) * 4;
            atomicAdd(&g_accA[c+0], ac.a0); atomicAdd(&g_accA[c+1], ac.a1);
            atomicAdd(&g_accA[c+2], ac.a2); atomicAdd(&g_accA[c+3], ac.a3);
            atomicAdd(&g_accB[c+0], ac.b0); atomicAdd(&g_accB[c+1], ac.b1);
            atomicAdd(&g_accB[c+2], ac.b2); atomicAdd(&g_accB[c+3], ac.b3);
            atomicAdd(&g_accP[c+0], ac.p0); atomicAdd(&g_accP[c+1], ac.p1);
            atomicAdd(&g_accP[c+2], ac.p2); atomicAdd(&g_accP[c+3], ac.p3);
        }
    }

    // Producer path must also hit the reduction's __syncthreads() calls.
    if (tid >= NCONS) {
        __syncthreads(); __syncthreads(); __syncthreads();
        __syncthreads(); __syncthreads(); __syncthreads();
        __syncthreads();
    }

    // ---------------- last-block finalize --------------------------------
    __threadfence();
    __syncthreads();
    if (tid == 0) {
        unsigned int prev = atomicAdd(&g_done, 1u);
        s_last = (prev == gridDim.x - 1);
    }
    __syncthreads();
    if (!s_last) return;

    __threadfence();
    if (tid < NCONS) {
        const int c = tid;
        const float Bf = (float)Bn;
        const float P  = g_accP[c];
        const float bn = pos_prop[c] * Bf;

        const bool  majIs1 = (P >= bn);
        const float n_maj  = majIs1 ? P : (Bf - P);
        const float n_min  = Bf - n_maj;
        const float w_maj  = bn / n_maj;
        const float w_min  = (n_min > 0.0f) ? (Bf - bn) / fmaxf(n_min, 1.0f) : 1.0f;
        const float w1 = majIs1 ? w_maj : w_min;
        const float w0 = majIs1 ? w_min : w_maj;

        float contrib = w0 * g_accA[c] + w1 * g_accB[c];

        g_accA[c] = 0.0f; g_accB[c] = 0.0f; g_accP[c] = 0.0f;
        if (c == 0) g_done = 0u;

        float* sh = (float*)dsm;
        sh[c] = contrib;
        __syncthreads();
        #pragma unroll
        for (int s = NCONS / 2; s > 0; s >>= 1) {
            if (c < s) sh[c] += sh[c + s];
            __syncthreads();
        }
        if (c == 0) out[0] = sh[0] / (Bf * (float)CCOLS);
    } else {
        // match finalize __syncthreads count (1 + 9 rounds)
        __syncthreads();
        #pragma unroll
        for (int s = NCONS / 2; s > 0; s >>= 1) __syncthreads();
    }
}

extern "C" void kernel_launch(void* const* d_in, const int* in_sizes, int n_in,
                              void* d_out, int out_size) {
    const float* pred = (const float*)d_in[0];
    const float* targ = (const float*)d_in[1];
    const float* pp   = (const float*)d_in[2];
    const int Cc = in_sizes[2];          // 512
    const int Bn = in_sizes[0] / Cc;     // 65536

    const int smem_bytes = NSTG * STG_F4 * sizeof(float4);   // 64 KB
    static bool configured = false;
    if (!configured) {
        cudaFuncSetAttribute(bl_pipe_kernel,
                             cudaFuncAttributeMaxDynamicSharedMemorySize, smem_bytes);
        configured = true;
    }
    bl_pipe_kernel<<<NBLK, NTHR, smem_bytes>>>((const float4*)pred,
                                               (const float4*)targ,
                                               pp, (float*)d_out, Bn);
}

// round 10
// speedup vs baseline: 1.7456x; 1.2628x over previous
#include <cuda_runtime.h>
#include <cstdint>

// BalancedLoss fused kernel, R10: L2-prefetch streaming.
// Per column c: A_c = sum (1-t)*softplus(x), B_c = sum t*(softplus(x)-x),
// P_c = sum t;  loss = sum_c (w0_c*A_c + w1_c*B_c) / (B*C).
// Contiguous 8KB chunks per CTA per iteration; cp.async.bulk.prefetch.L2
// runs 2 grid-strides ahead so demand LDGs are L2 hits (~270cyc), shrinking
// the Little's-law in-flight requirement that capped the register version.

#define CCOLS 512
#define C4    128        // float4 groups per row
#define NBLK  740        // 5 CTAs/SM
#define NTHR  256
#define CHUNK_F4 512     // float4 per tensor per chunk (8 KB)
#define PF_D  2          // prefetch distance in grid-strides
#define REPL  4          // accumulator replicas (atomic contention)

__device__ float g_accA[REPL][CCOLS];
__device__ float g_accB[REPL][CCOLS];
__device__ float g_accP[REPL][CCOLS];
__device__ unsigned int g_done;

__device__ __forceinline__ void prefetch_l2(const void* p, uint32_t bytes) {
    asm volatile("cp.async.bulk.prefetch.L2.global [%0], %1;"
                 :: "l"(p), "r"(bytes) : "memory");
}

__device__ __forceinline__ float softplus_f(float x) {
    return fmaxf(x, 0.0f) + __logf(1.0f + __expf(-fabsf(x)));
}

struct Acc {
    float a0, a1, a2, a3, b0, b1, b2, b3, p0, p1, p2, p3;
};

__device__ __forceinline__ void bl_acc(Acc& ac, const float4& x, const float4& t) {
    float s;
    s = softplus_f(x.x); ac.a0 += s - s*t.x; ac.b0 += (s - x.x)*t.x; ac.p0 += t.x;
    s = softplus_f(x.y); ac.a1 += s - s*t.y; ac.b1 += (s - x.y)*t.y; ac.p1 += t.y;
    s = softplus_f(x.z); ac.a2 += s - s*t.z; ac.b2 += (s - x.z)*t.z; ac.p2 += t.z;
    s = softplus_f(x.w); ac.a3 += s - s*t.w; ac.b3 += (s - x.w)*t.w; ac.p3 += t.w;
}

__global__ __launch_bounds__(NTHR, 5)
void bl_pf_kernel(const float4* __restrict__ pred,
                  const float4* __restrict__ targ,
                  const float* __restrict__ pos_prop,
                  float* __restrict__ out,
                  int Bn) {
    const int tid  = threadIdx.x;
    const int grid = gridDim.x;
    const int total_f4 = Bn * C4;
    const int nchunk = total_f4 / CHUNK_F4;

    Acc ac = {0.f,0.f,0.f,0.f, 0.f,0.f,0.f,0.f, 0.f,0.f,0.f,0.f};

    for (int c = blockIdx.x; c < nchunk; c += grid) {
        if (tid == 0) {
            const int pc = c + PF_D * grid;
            if (pc < nchunk) {
                prefetch_l2(pred + (size_t)pc * CHUNK_F4, CHUNK_F4 * 16);
                prefetch_l2(targ + (size_t)pc * CHUNK_F4, CHUNK_F4 * 16);
            }
        }
        const size_t base = (size_t)c * CHUNK_F4;
        // CHUNK_F4 (512) and NTHR (256) are multiples of 128, so the column
        // group of both reads is tid & 127 — accumulator mapping is stable.
        const float4 x0 = __ldcs(pred + base + tid);
        const float4 t0 = __ldcs(targ + base + tid);
        const float4 x1 = __ldcs(pred + base + tid + NTHR);
        const float4 t1 = __ldcs(targ + base + tid + NTHR);
        bl_acc(ac, x0, t0);
        bl_acc(ac, x1, t1);
    }
    // tail f4 groups (total_f4 % CHUNK_F4 != 0): block 0, column-preserving
    if (blockIdx.x == 0) {
        for (int i = nchunk * CHUNK_F4 + tid; i < total_f4; i += NTHR) {
            // (i - tid) multiple of CHUNK_F4 => col group = tid&127 preserved
            const float4 x = __ldg(pred + i);
            const float4 t = __ldg(targ + i);
            bl_acc(ac, x, t);
        }
    }

    // ---- intra-block reduction over the 2 row-lanes ----
    __shared__ float4 sbuf[NTHR];
    const int rlane = tid >> 7;   // 0..1

    sbuf[tid] = make_float4(ac.a0, ac.a1, ac.a2, ac.a3);
    __syncthreads();
    if (rlane == 0) {
        float4 u = sbuf[tid + 128];
        ac.a0 += u.x; ac.a1 += u.y; ac.a2 += u.z; ac.a3 += u.w;
    }
    __syncthreads();
    sbuf[tid] = make_float4(ac.b0, ac.b1, ac.b2, ac.b3);
    __syncthreads();
    if (rlane == 0) {
        float4 u = sbuf[tid + 128];
        ac.b0 += u.x; ac.b1 += u.y; ac.b2 += u.z; ac.b3 += u.w;
    }
    __syncthreads();
    sbuf[tid] = make_float4(ac.p0, ac.p1, ac.p2, ac.p3);
    __syncthreads();
    if (rlane == 0) {
        float4 u = sbuf[tid + 128];
        ac.p0 += u.x; ac.p1 += u.y; ac.p2 += u.z; ac.p3 += u.w;

        const int rep = blockIdx.x & (REPL - 1);
        const int c = (tid & (C4 - 1)) * 4;
        atomicAdd(&g_accA[rep][c+0], ac.a0); atomicAdd(&g_accA[rep][c+1], ac.a1);
        atomicAdd(&g_accA[rep][c+2], ac.a2); atomicAdd(&g_accA[rep][c+3], ac.a3);
        atomicAdd(&g_accB[rep][c+0], ac.b0); atomicAdd(&g_accB[rep][c+1], ac.b1);
        atomicAdd(&g_accB[rep][c+2], ac.b2); atomicAdd(&g_accB[rep][c+3], ac.b3);
        atomicAdd(&g_accP[rep][c+0], ac.p0); atomicAdd(&g_accP[rep][c+1], ac.p1);
        atomicAdd(&g_accP[rep][c+2], ac.p2); atomicAdd(&g_accP[rep][c+3], ac.p3);
    }

    // ---- last-block finalize ----
    __shared__ bool s_last;
    __threadfence();
    __syncthreads();
    if (tid == 0) {
        unsigned int prev = atomicAdd(&g_done, 1u);
        s_last = (prev == gridDim.x - 1);
    }
    __syncthreads();
    if (!s_last) return;

    __threadfence();
    {
        const float Bf = (float)Bn;
        float contrib = 0.0f;

        #pragma unroll
        for (int k = 0; k < 2; k++) {
            const int c = tid + k * NTHR;     // covers 512 columns
            float A = 0.f, Bv = 0.f, P = 0.f;
            #pragma unroll
            for (int r = 0; r < REPL; r++) {
                A += g_accA[r][c]; Bv += g_accB[r][c]; P += g_accP[r][c];
                g_accA[r][c] = 0.0f; g_accB[r][c] = 0.0f; g_accP[r][c] = 0.0f;
            }
            const float bn = pos_prop[c] * Bf;
            const bool  majIs1 = (P >= bn);
            const float n_maj  = majIs1 ? P : (Bf - P);
            const float n_min  = Bf - n_maj;
            const float w_maj  = bn / n_maj;
            const float w_min  = (n_min > 0.0f) ? (Bf - bn) / fmaxf(n_min, 1.0f)
                                                : 1.0f;
            const float w1 = majIs1 ? w_maj : w_min;
            const float w0 = majIs1 ? w_min : w_maj;
            contrib += w0 * A + w1 * Bv;
        }
        if (tid == 0) g_done = 0u;

        __shared__ float sh[NTHR];
        sh[tid] = contrib;
        __syncthreads();
        #pragma unroll
        for (int s = NTHR / 2; s > 0; s >>= 1) {
            if (tid < s) sh[tid] += sh[tid + s];
            __syncthreads();
        }
        if (tid == 0) out[0] = sh[0] / (Bf * (float)CCOLS);
    }
}

extern "C" void kernel_launch(void* const* d_in, const int* in_sizes, int n_in,
                              void* d_out, int out_size) {
    const float* pred = (const float*)d_in[0];
    const float* targ = (const float*)d_in[1];
    const float* pp   = (const float*)d_in[2];
    const int Cc = in_sizes[2];          // 512
    const int Bn = in_sizes[0] / Cc;     // 65536

    bl_pf_kernel<<<NBLK, NTHR>>>((const float4*)pred, (const float4*)targ,
                                 pp, (float*)d_out, Bn);
}